// round 13
// baseline (speedup 1.0000x reference)
#include <cuda_runtime.h>

#define THREADS 256
#define NWARP (THREADS / 32)
#define TOPK 5
#define NCAT 8
#define CAPG 64
#define FULLM 0xffffffffu
#define L2E 1.4426950408889634f
#define LN2 0.6931471805599453f
#define NEG_INF (-__int_as_float(0x7f800000))
#define THRESH 3.25f

__device__ float g_rowloss[8192];
__device__ float g_psum[8192];
__device__ int   g_rdone[8192];
__device__ int   g_ccnt[8192];
__device__ float g_cvals[8192][CAPG];
__device__ int   g_cidx[8192][CAPG];
__device__ unsigned int g_done = 0;

__device__ __forceinline__ float ex2f(float x) {
    float y; asm("ex2.approx.ftz.f32 %0, %1;" : "=f"(y) : "f"(x)); return y;
}
__device__ __forceinline__ float lg2f(float x) {
    float y; asm("lg2.approx.ftz.f32 %0, %1;" : "=f"(y) : "f"(x)); return y;
}

__device__ __forceinline__ void insert5(float (&tv)[TOPK], int (&ti)[TOPK], float v, int idx) {
    tv[TOPK - 1] = v; ti[TOPK - 1] = idx;
#pragma unroll
    for (int k = TOPK - 1; k > 0; --k) {
        if (tv[k] > tv[k - 1]) {
            float tf = tv[k]; tv[k] = tv[k - 1]; tv[k - 1] = tf;
            int   tt = ti[k]; ti[k] = ti[k - 1]; ti[k - 1] = tt;
        }
    }
}

__global__ void __launch_bounds__(THREADS, 8)
hier_loss_fused(const float* __restrict__ logits,
                const int* __restrict__ labels,
                const int* __restrict__ catlab,
                const int* __restrict__ c2c,
                float* __restrict__ out,
                int V, int ncmd, int B)
{
    const int bx  = blockIdx.x;
    const int b   = bx >> 1;            // row
    const int h   = bx & 1;             // half
    const int tid = threadIdx.x;
    const float* row = logits + (size_t)b * (size_t)V;

    __shared__ int   s_c2c[64];
    __shared__ float s_wS[NWARP];
    __shared__ float s_cat[NCAT];
    __shared__ int   s_fin;
    __shared__ int   s_isLast;
    __shared__ float s_red[THREADS];

    if (tid < 64 && tid < ncmd) s_c2c[tid] = c2c[tid];

    const float negC = -__ldg(row) * L2E;       // common base for both halves
    float s0 = 0.f, s1 = 0.f;

    const int mis = (int)(((size_t)b * (size_t)V) & 3);
    const int pre = (4 - mis) & 3;
    const int nv4 = (V - pre) >> 2;             // aligned float4 count
    const int split = ((nv4 / 2) / (4 * THREADS)) * (4 * THREADS);
    const int f4lo = h ? split : 0;
    const int f4hi = h ? nv4 : split;
    const int nIter = (f4hi - f4lo) / (4 * THREADS);
    const float4* __restrict__ p4base = (const float4*)(row + pre);
    const float4* __restrict__ p4 = p4base + f4lo + tid;

#define PUSHG(val, ei)                                                        \
    do {                                                                      \
        if ((val) > THRESH) {                                                 \
            int pos = atomicAdd(&g_ccnt[b], 1);                               \
            if (pos < CAPG) { g_cvals[b][pos] = (val); g_cidx[b][pos] = (ei); } \
        }                                                                     \
    } while (0)

    // ---- head (pre <= 3 elements): half 0 only ----
    if (h == 0 && tid < pre) {
        float x = __ldg(row + tid);
        s0 += ex2f(fmaf(x, L2E, negC));
        PUSHG(x, tid);
    }

    // ---- main vector loop: 4 x float4 = 16 elements / thread / iter (R9 shape) ----
    for (int j = nIter; j > 0; --j) {
        float4 v0 = __ldg(p4);
        float4 v1 = __ldg(p4 + THREADS);
        float4 v2 = __ldg(p4 + 2 * THREADS);
        float4 v3 = __ldg(p4 + 3 * THREADS);

        float imax = fmaxf(
            fmaxf(fmaxf(fmaxf(v0.x, v0.y), fmaxf(v0.z, v0.w)),
                  fmaxf(fmaxf(v1.x, v1.y), fmaxf(v1.z, v1.w))),
            fmaxf(fmaxf(fmaxf(v2.x, v2.y), fmaxf(v2.z, v2.w)),
                  fmaxf(fmaxf(v3.x, v3.y), fmaxf(v3.z, v3.w))));

        if (__any_sync(FULLM, imax > THRESH)) {
            if (imax > THRESH) {
                int bi0 = pre + 4 * (int)(p4 - p4base);
                int bi1 = bi0 + 4 * THREADS;
                int bi2 = bi0 + 8 * THREADS;
                int bi3 = bi0 + 12 * THREADS;
                PUSHG(v0.x, bi0 + 0); PUSHG(v0.y, bi0 + 1);
                PUSHG(v0.z, bi0 + 2); PUSHG(v0.w, bi0 + 3);
                PUSHG(v1.x, bi1 + 0); PUSHG(v1.y, bi1 + 1);
                PUSHG(v1.z, bi1 + 2); PUSHG(v1.w, bi1 + 3);
                PUSHG(v2.x, bi2 + 0); PUSHG(v2.y, bi2 + 1);
                PUSHG(v2.z, bi2 + 2); PUSHG(v2.w, bi2 + 3);
                PUSHG(v3.x, bi3 + 0); PUSHG(v3.y, bi3 + 1);
                PUSHG(v3.z, bi3 + 2); PUSHG(v3.w, bi3 + 3);
            }
        }

        s0 += ex2f(fmaf(v0.x, L2E, negC));
        s1 += ex2f(fmaf(v0.y, L2E, negC));
        s0 += ex2f(fmaf(v0.z, L2E, negC));
        s1 += ex2f(fmaf(v0.w, L2E, negC));
        s0 += ex2f(fmaf(v1.x, L2E, negC));
        s1 += ex2f(fmaf(v1.y, L2E, negC));
        s0 += ex2f(fmaf(v1.z, L2E, negC));
        s1 += ex2f(fmaf(v1.w, L2E, negC));
        s0 += ex2f(fmaf(v2.x, L2E, negC));
        s1 += ex2f(fmaf(v2.y, L2E, negC));
        s0 += ex2f(fmaf(v2.z, L2E, negC));
        s1 += ex2f(fmaf(v2.w, L2E, negC));
        s0 += ex2f(fmaf(v3.x, L2E, negC));
        s1 += ex2f(fmaf(v3.y, L2E, negC));
        s0 += ex2f(fmaf(v3.z, L2E, negC));
        s1 += ex2f(fmaf(v3.w, L2E, negC));

        p4 += 4 * THREADS;
    }

    // ---- float4 remainder of this half (predicated, ballot-free) ----
    for (int f4 = f4lo + nIter * 4 * THREADS + tid; f4 < f4hi; f4 += THREADS) {
        float4 a = __ldg(p4base + f4);
        int bi = pre + 4 * f4;
        s0 += ex2f(fmaf(a.x, L2E, negC));
        s1 += ex2f(fmaf(a.y, L2E, negC));
        s0 += ex2f(fmaf(a.z, L2E, negC));
        s1 += ex2f(fmaf(a.w, L2E, negC));
        PUSHG(a.x, bi + 0); PUSHG(a.y, bi + 1);
        PUSHG(a.z, bi + 2); PUSHG(a.w, bi + 3);
    }

    // ---- scalar tail (<= 3 elements): half 1 only ----
    if (h == 1) {
        for (int i = pre + nv4 * 4 + tid; i < V; i += THREADS) {
            float x = __ldg(row + i);
            s0 += ex2f(fmaf(x, L2E, negC));
            PUSHG(x, i);
        }
    }
#undef PUSHG

    // ---- block reduce partial exp-sum ----
    float s = s0 + s1;
#pragma unroll
    for (int off = 16; off; off >>= 1)
        s += __shfl_xor_sync(FULLM, s, off);

    const int lane = tid & 31;
    const int w    = tid >> 5;
    if (lane == 0) s_wS[w] = s;
    __syncthreads();

    if (tid == 0) {
        float sf = 0.0f;
#pragma unroll
        for (int ww = 0; ww < NWARP; ++ww) sf += s_wS[ww];
        atomicAdd(&g_psum[b], sf);              // 2 contributions: commutative => deterministic
        __threadfence();
        int prev = atomicAdd(&g_rdone[b], 1);
        s_fin = (prev == 1);                    // second arriver finishes the row
    }
    __syncthreads();

    // ---- finisher CTA: top-5 + row loss + per-row state reset ----
    if (s_fin && w == 0) {
        __threadfence();                        // acquire peer CTA's writes

        float tv[TOPK]; int ti[TOPK];
#pragma unroll
        for (int k = 0; k < TOPK; ++k) { tv[k] = NEG_INF; ti[k] = 0; }

        int cnt = *(volatile int*)&g_ccnt[b];
        if (cnt >= TOPK && cnt <= CAPG) {
            for (int base = 0; base < cnt; base += 32) {
                int i = base + lane;
                float x = (i < cnt) ? *(volatile float*)&g_cvals[b][i] : NEG_INF;
                int  id = (i < cnt) ? *(volatile int*)&g_cidx[b][i]    : 0;
                unsigned bal = __ballot_sync(FULLM, x > tv[TOPK - 1]);
                while (bal) {
                    int L = __ffs(bal) - 1; bal &= bal - 1;
                    float xv = __shfl_sync(FULLM, x, L);
                    int   iv = __shfl_sync(FULLM, id, L);
                    if (xv > tv[TOPK - 1]) insert5(tv, ti, xv, iv);
                }
            }
        } else {
            // exact fallback (astronomically rare): full-row online top-5
            for (int i0 = 0; i0 < V; i0 += 32) {
                int i = i0 + lane;
                float x = (i < V) ? __ldg(row + i) : NEG_INF;
                unsigned bal = __ballot_sync(FULLM, x > tv[TOPK - 1]);
                while (bal) {
                    int L = __ffs(bal) - 1; bal &= bal - 1;
                    float xv = __shfl_sync(FULLM, x, L);
                    if (xv > tv[TOPK - 1]) insert5(tv, ti, xv, i0 + L);
                }
            }
        }

        if (lane == 0) {
            float sf = *(volatile float*)&g_psum[b];

            float lse  = (-negC + lg2f(sf)) * LN2;
            int   lab  = __ldg(labels + b);
            float xlab = __ldg(row + lab);
            float nll_cmd = lse - xlab;

#pragma unroll
            for (int c = 0; c < NCAT; ++c) s_cat[c] = 0.0f;
#pragma unroll
            for (int k = 0; k < TOPK; ++k)
                s_cat[s_c2c[ti[k] % ncmd]] += tv[k];

            float mxc = s_cat[0];
#pragma unroll
            for (int c = 1; c < NCAT; ++c) mxc = fmaxf(mxc, s_cat[c]);
            float ssum = 0.0f;
#pragma unroll
            for (int c = 0; c < NCAT; ++c) ssum += ex2f((s_cat[c] - mxc) * L2E);
            int   cl = __ldg(catlab + b);
            float nll_cat = lg2f(ssum) * LN2 + mxc - s_cat[cl];

            g_rowloss[b] = 0.6f * nll_cmd + 0.4f * nll_cat;

            // self-clean per-row state for next graph replay
            g_psum[b]  = 0.0f;
            g_ccnt[b]  = 0;
            g_rdone[b] = 0;
        }
    }
    __syncthreads();

    // ---- completion protocol over all 2B CTAs ----
    if (tid == 0) {
        __threadfence();
        unsigned int prev = atomicAdd(&g_done, 1u);
        s_isLast = (prev == (unsigned int)(gridDim.x - 1));
    }
    __syncthreads();

    if (s_isLast) {
        __threadfence();
        float a = 0.0f;
        for (int i = tid; i < B; i += THREADS) a += g_rowloss[i];
        s_red[tid] = a;
        __syncthreads();
#pragma unroll
        for (int off = THREADS / 2; off; off >>= 1) {
            if (tid < off) s_red[tid] += s_red[tid + off];
            __syncthreads();
        }
        if (tid == 0) {
            out[0] = s_red[0] * (1.0f / (float)B);
            atomicExch(&g_done, 0u);
        }
    }
}

extern "C" void kernel_launch(void* const* d_in, const int* in_sizes, int n_in,
                              void* d_out, int out_size)
{
    const float* logits = (const float*)d_in[0];
    const int*   labels = (const int*)d_in[1];
    const int*   catlab = (const int*)d_in[2];
    const int*   c2c    = (const int*)d_in[3];

    const int B    = in_sizes[1];
    const int V    = in_sizes[0] / B;
    const int ncmd = in_sizes[3];

    hier_loss_fused<<<2 * B, THREADS>>>(logits, labels, catlab, c2c,
                                        (float*)d_out, V, ncmd, B);
}

// round 14
// speedup vs baseline: 1.0643x; 1.0643x over previous
#include <cuda_runtime.h>

#define THREADS 256
#define NWARP (THREADS / 32)
#define TOPK 5
#define NCAT 8
#define CAP 512
#define FULLM 0xffffffffu
#define L2E 1.4426950408889634f
#define LN2 0.6931471805599453f
#define NEG_INF (-__int_as_float(0x7f800000))
#define THRESH 3.25f

__device__ float g_rowloss[8192];
__device__ unsigned int g_done = 0;

__device__ __forceinline__ float ex2f(float x) {
    float y; asm("ex2.approx.ftz.f32 %0, %1;" : "=f"(y) : "f"(x)); return y;
}
__device__ __forceinline__ float lg2f(float x) {
    float y; asm("lg2.approx.ftz.f32 %0, %1;" : "=f"(y) : "f"(x)); return y;
}

__device__ __forceinline__ void insert5(float (&tv)[TOPK], int (&ti)[TOPK], float v, int idx) {
    tv[TOPK - 1] = v; ti[TOPK - 1] = idx;
#pragma unroll
    for (int k = TOPK - 1; k > 0; --k) {
        if (tv[k] > tv[k - 1]) {
            float tf = tv[k]; tv[k] = tv[k - 1]; tv[k - 1] = tf;
            int   tt = ti[k]; ti[k] = ti[k - 1]; ti[k - 1] = tt;
        }
    }
}

__global__ void __launch_bounds__(THREADS, 8)
hier_loss_fused(const float* __restrict__ logits,
                const int* __restrict__ labels,
                const int* __restrict__ catlab,
                const int* __restrict__ c2c,
                float* __restrict__ out,
                int V, int ncmd, int B)
{
    const int b   = blockIdx.x;
    const int tid = threadIdx.x;
    const float* row = logits + (size_t)b * (size_t)V;

    __shared__ int   s_c2c[64];
    __shared__ float s_wS[NWARP];
    __shared__ float s_vals[CAP];
    __shared__ int   s_idx[CAP];
    __shared__ int   s_cnt;
    __shared__ float s_cat[NCAT];
    __shared__ int   s_isLast;
    __shared__ float s_red[THREADS];
    __shared__ float s_xlab;          // prefetched row[label[b]]
    __shared__ int   s_cl;            // prefetched category label

    if (tid < 64 && tid < ncmd) s_c2c[tid] = c2c[tid];
    if (tid == 0) {
        s_cnt = 0;
        // tail-latency trim: issue the dependent label gathers NOW so the
        // 2x ~600-cycle round trips hide under the streaming loop instead of
        // serializing on the CTA's critical tail.
        int lab = __ldg(labels + b);
        s_xlab  = __ldg(row + lab);
        s_cl    = __ldg(catlab + b);
    }
    __syncthreads();

    const float negC = -__ldg(row) * L2E;      // block-wide base (log2 domain)
    float s0 = 0.f, s1 = 0.f;

    const int mis = (int)(((size_t)b * (size_t)V) & 3);
    const int pre = (4 - mis) & 3;
    const int nv4 = (V - pre) >> 2;
    const int nIterV = nv4 / (4 * THREADS);
    const int vecElems = nIterV * 16 * THREADS;
    const float4* __restrict__ p4base = (const float4*)(row + pre);
    const float4* __restrict__ p4 = p4base + tid;

#define PUSH(val, ei)                                                         \
    do {                                                                      \
        if ((val) > THRESH) {                                                 \
            int pos = atomicAdd(&s_cnt, 1);                                   \
            if (pos < CAP) { s_vals[pos] = (val); s_idx[pos] = (ei); }        \
        }                                                                     \
    } while (0)

    // ---- head (pre <= 3 elements) ----
    if (tid < pre) {
        float x = __ldg(row + tid);
        s0 += ex2f(fmaf(x, L2E, negC));
        PUSH(x, tid);
    }

    // ---- main vector loop: 4 x float4 = 16 elements / thread / iter ----
    for (int j = nIterV; j > 0; --j) {
        float4 v0 = __ldcs(p4);
        float4 v1 = __ldcs(p4 + THREADS);
        float4 v2 = __ldcs(p4 + 2 * THREADS);
        float4 v3 = __ldcs(p4 + 3 * THREADS);

        float imax = fmaxf(
            fmaxf(fmaxf(fmaxf(v0.x, v0.y), fmaxf(v0.z, v0.w)),
                  fmaxf(fmaxf(v1.x, v1.y), fmaxf(v1.z, v1.w))),
            fmaxf(fmaxf(fmaxf(v2.x, v2.y), fmaxf(v2.z, v2.w)),
                  fmaxf(fmaxf(v3.x, v3.y), fmaxf(v3.z, v3.w))));

        // rare candidate-collection region (indices via pointer diff, cold only)
        if (__any_sync(FULLM, imax > THRESH)) {
            if (imax > THRESH) {
                int e0 = (int)(p4 - p4base);               // float4 index of v0
                int bi0 = pre + 4 * e0;
                int bi1 = bi0 + 4 * THREADS;
                int bi2 = bi0 + 8 * THREADS;
                int bi3 = bi0 + 12 * THREADS;
                PUSH(v0.x, bi0 + 0); PUSH(v0.y, bi0 + 1);
                PUSH(v0.z, bi0 + 2); PUSH(v0.w, bi0 + 3);
                PUSH(v1.x, bi1 + 0); PUSH(v1.y, bi1 + 1);
                PUSH(v1.z, bi1 + 2); PUSH(v1.w, bi1 + 3);
                PUSH(v2.x, bi2 + 0); PUSH(v2.y, bi2 + 1);
                PUSH(v2.z, bi2 + 2); PUSH(v2.w, bi2 + 3);
                PUSH(v3.x, bi3 + 0); PUSH(v3.y, bi3 + 1);
                PUSH(v3.z, bi3 + 2); PUSH(v3.w, bi3 + 3);
            }
        }

        // hot exp-sum: FFMA + MUFU + FADD per element
        s0 += ex2f(fmaf(v0.x, L2E, negC));
        s1 += ex2f(fmaf(v0.y, L2E, negC));
        s0 += ex2f(fmaf(v0.z, L2E, negC));
        s1 += ex2f(fmaf(v0.w, L2E, negC));
        s0 += ex2f(fmaf(v1.x, L2E, negC));
        s1 += ex2f(fmaf(v1.y, L2E, negC));
        s0 += ex2f(fmaf(v1.z, L2E, negC));
        s1 += ex2f(fmaf(v1.w, L2E, negC));
        s0 += ex2f(fmaf(v2.x, L2E, negC));
        s1 += ex2f(fmaf(v2.y, L2E, negC));
        s0 += ex2f(fmaf(v2.z, L2E, negC));
        s1 += ex2f(fmaf(v2.w, L2E, negC));
        s0 += ex2f(fmaf(v3.x, L2E, negC));
        s1 += ex2f(fmaf(v3.y, L2E, negC));
        s0 += ex2f(fmaf(v3.z, L2E, negC));
        s1 += ex2f(fmaf(v3.w, L2E, negC));

        p4 += 4 * THREADS;
    }

    // ---- scalar tail: [pre + vecElems, V) ----
    for (int i = pre + vecElems + tid; i < V; i += THREADS) {
        float x = __ldg(row + i);
        s0 += ex2f(fmaf(x, L2E, negC));
        PUSH(x, i);
    }
#undef PUSH

    // ---- warp reduce s (uniform base for the whole block) ----
    float s = s0 + s1;
#pragma unroll
    for (int off = 16; off; off >>= 1)
        s += __shfl_xor_sync(FULLM, s, off);

    const int lane = tid & 31;
    const int w    = tid >> 5;
    if (lane == 0) s_wS[w] = s;
    __syncthreads();

    // ---- warp 0: top-5 selection + final math ----
    if (w == 0) {
        float tv[TOPK]; int ti[TOPK];
#pragma unroll
        for (int k = 0; k < TOPK; ++k) { tv[k] = NEG_INF; ti[k] = 0; }

        int cnt = s_cnt;
        if (cnt >= TOPK && cnt <= CAP) {
            for (int base = 0; base < cnt; base += 32) {
                int i = base + lane;
                float x = (i < cnt) ? s_vals[i] : NEG_INF;
                int  id = (i < cnt) ? s_idx[i]  : 0;
                unsigned bal = __ballot_sync(FULLM, x > tv[TOPK - 1]);
                while (bal) {
                    int L = __ffs(bal) - 1; bal &= bal - 1;
                    float xv = __shfl_sync(FULLM, x, L);
                    int   iv = __shfl_sync(FULLM, id, L);
                    if (xv > tv[TOPK - 1]) insert5(tv, ti, xv, iv);
                }
            }
        } else {
            // exact fallback (astronomically rare): full-row online top-5
            for (int i0 = 0; i0 < V; i0 += 32) {
                int i = i0 + lane;
                float x = (i < V) ? __ldg(row + i) : NEG_INF;
                unsigned bal = __ballot_sync(FULLM, x > tv[TOPK - 1]);
                while (bal) {
                    int L = __ffs(bal) - 1; bal &= bal - 1;
                    float xv = __shfl_sync(FULLM, x, L);
                    if (xv > tv[TOPK - 1]) insert5(tv, ti, xv, i0 + L);
                }
            }
        }

        if (lane == 0) {
            float sf = 0.0f;
            for (int ww = 0; ww < NWARP; ++ww) sf += s_wS[ww];

            float lse  = (-negC + lg2f(sf)) * LN2;
            float nll_cmd = lse - s_xlab;          // prefetched at kernel start

#pragma unroll
            for (int c = 0; c < NCAT; ++c) s_cat[c] = 0.0f;
#pragma unroll
            for (int k = 0; k < TOPK; ++k)
                s_cat[s_c2c[ti[k] % ncmd]] += tv[k];

            float mxc = s_cat[0];
#pragma unroll
            for (int c = 1; c < NCAT; ++c) mxc = fmaxf(mxc, s_cat[c]);
            float ssum = 0.0f;
#pragma unroll
            for (int c = 0; c < NCAT; ++c) ssum += ex2f((s_cat[c] - mxc) * L2E);
            float nll_cat = lg2f(ssum) * LN2 + mxc - s_cat[s_cl];

            g_rowloss[b] = 0.6f * nll_cmd + 0.4f * nll_cat;

            __threadfence();
            unsigned int prev = atomicAdd(&g_done, 1u);
            s_isLast = (prev == (unsigned int)(gridDim.x - 1));
        }
    }
    __syncthreads();

    // ---- fused deterministic final reduction (last block) ----
    if (s_isLast) {
        __threadfence();
        float a = 0.0f;
        for (int i = tid; i < B; i += THREADS) a += g_rowloss[i];
        s_red[tid] = a;
        __syncthreads();
#pragma unroll
        for (int off = THREADS / 2; off; off >>= 1) {
            if (tid < off) s_red[tid] += s_red[tid + off];
            __syncthreads();
        }
        if (tid == 0) {
            out[0] = s_red[0] * (1.0f / (float)B);
            atomicExch(&g_done, 0u);
        }
    }
}

extern "C" void kernel_launch(void* const* d_in, const int* in_sizes, int n_in,
                              void* d_out, int out_size)
{
    const float* logits = (const float*)d_in[0];
    const int*   labels = (const int*)d_in[1];
    const int*   catlab = (const int*)d_in[2];
    const int*   c2c    = (const int*)d_in[3];

    const int B    = in_sizes[1];
    const int V    = in_sizes[0] / B;
    const int ncmd = in_sizes[3];

    hier_loss_fused<<<B, THREADS>>>(logits, labels, catlab, c2c,
                                    (float*)d_out, V, ncmd, B);
}

// round 15
// speedup vs baseline: 1.0771x; 1.0120x over previous
#include <cuda_runtime.h>

#define THREADS 256
#define NWARP (THREADS / 32)
#define TOPK 5
#define NCAT 8
#define CAP 512
#define GRID 1216           /* 152 SMs x 8 CTAs */
#define FULLM 0xffffffffu
#define L2E 1.4426950408889634f
#define LN2 0.6931471805599453f
#define NEG_INF (-__int_as_float(0x7f800000))
#define THRESH 3.25f

__device__ float g_rowloss[8192];
__device__ unsigned int g_done = 0;

__device__ __forceinline__ float ex2f(float x) {
    float y; asm("ex2.approx.ftz.f32 %0, %1;" : "=f"(y) : "f"(x)); return y;
}
__device__ __forceinline__ float lg2f(float x) {
    float y; asm("lg2.approx.ftz.f32 %0, %1;" : "=f"(y) : "f"(x)); return y;
}

__device__ __forceinline__ void insert5(float (&tv)[TOPK], int (&ti)[TOPK], float v, int idx) {
    tv[TOPK - 1] = v; ti[TOPK - 1] = idx;
#pragma unroll
    for (int k = TOPK - 1; k > 0; --k) {
        if (tv[k] > tv[k - 1]) {
            float tf = tv[k]; tv[k] = tv[k - 1]; tv[k - 1] = tf;
            int   tt = ti[k]; ti[k] = ti[k - 1]; ti[k - 1] = tt;
        }
    }
}

__global__ void __launch_bounds__(THREADS, 8)
hier_loss_fused(const float* __restrict__ logits,
                const int* __restrict__ labels,
                const int* __restrict__ catlab,
                const int* __restrict__ c2c,
                float* __restrict__ out,
                int V, int ncmd, int B)
{
    const int tid  = threadIdx.x;
    const int lane = tid & 31;
    const int w    = tid >> 5;

    __shared__ int   s_c2c[64];
    __shared__ float s_wS[NWARP];
    __shared__ float s_vals[CAP];
    __shared__ int   s_idx[CAP];
    __shared__ int   s_cnt;
    __shared__ float s_cat[NCAT];
    __shared__ int   s_isLast;
    __shared__ float s_red[THREADS];
    __shared__ float s_xlab;          // prefetched row[label[b]]
    __shared__ int   s_cl;            // prefetched category label

    if (tid < 64 && tid < ncmd) s_c2c[tid] = c2c[tid];
    if (tid == 0) s_cnt = 0;
    __syncthreads();

    // ================= persistent row loop =================
    for (int b = blockIdx.x; b < B; b += gridDim.x) {
        const float* row = logits + (size_t)b * (size_t)V;

        // tail-latency trim: the epilogue's two dependent label gathers are
        // issued NOW (tid 0) so their ~2x600-cycle round trips hide under this
        // row's streaming loop. Visible to warp 0 after barrier (A).
        if (tid == 0) {
            int lab = __ldg(labels + b);
            s_xlab  = __ldg(row + lab);
            s_cl    = __ldg(catlab + b);
        }

        const float negC = -__ldg(row) * L2E;  // block-wide base (log2 domain)
        float s0 = 0.f, s1 = 0.f;

        const int mis = (int)(((size_t)b * (size_t)V) & 3);
        const int pre = (4 - mis) & 3;
        const int nv4 = (V - pre) >> 2;
        const int nIterV = nv4 / (4 * THREADS);
        const int vecElems = nIterV * 16 * THREADS;
        const float4* __restrict__ p4base = (const float4*)(row + pre);
        const float4* __restrict__ p4 = p4base + tid;

#define PUSH(val, ei)                                                         \
        do {                                                                  \
            if ((val) > THRESH) {                                             \
                int pos = atomicAdd(&s_cnt, 1);                               \
                if (pos < CAP) { s_vals[pos] = (val); s_idx[pos] = (ei); }    \
            }                                                                 \
        } while (0)

        // ---- head (pre <= 3 elements) ----
        if (tid < pre) {
            float x = __ldg(row + tid);
            s0 += ex2f(fmaf(x, L2E, negC));
            PUSH(x, tid);
        }

        // ---- main vector loop: 4 x float4 = 16 elements / thread / iter ----
        for (int j = nIterV; j > 0; --j) {
            float4 v0 = __ldcs(p4);
            float4 v1 = __ldcs(p4 + THREADS);
            float4 v2 = __ldcs(p4 + 2 * THREADS);
            float4 v3 = __ldcs(p4 + 3 * THREADS);

            float imax = fmaxf(
                fmaxf(fmaxf(fmaxf(v0.x, v0.y), fmaxf(v0.z, v0.w)),
                      fmaxf(fmaxf(v1.x, v1.y), fmaxf(v1.z, v1.w))),
                fmaxf(fmaxf(fmaxf(v2.x, v2.y), fmaxf(v2.z, v2.w)),
                      fmaxf(fmaxf(v3.x, v3.y), fmaxf(v3.z, v3.w))));

            // rare candidate-collection region (cold)
            if (__any_sync(FULLM, imax > THRESH)) {
                if (imax > THRESH) {
                    int e0 = (int)(p4 - p4base);
                    int bi0 = pre + 4 * e0;
                    int bi1 = bi0 + 4 * THREADS;
                    int bi2 = bi0 + 8 * THREADS;
                    int bi3 = bi0 + 12 * THREADS;
                    PUSH(v0.x, bi0 + 0); PUSH(v0.y, bi0 + 1);
                    PUSH(v0.z, bi0 + 2); PUSH(v0.w, bi0 + 3);
                    PUSH(v1.x, bi1 + 0); PUSH(v1.y, bi1 + 1);
                    PUSH(v1.z, bi1 + 2); PUSH(v1.w, bi1 + 3);
                    PUSH(v2.x, bi2 + 0); PUSH(v2.y, bi2 + 1);
                    PUSH(v2.z, bi2 + 2); PUSH(v2.w, bi2 + 3);
                    PUSH(v3.x, bi3 + 0); PUSH(v3.y, bi3 + 1);
                    PUSH(v3.z, bi3 + 2); PUSH(v3.w, bi3 + 3);
                }
            }

            // hot exp-sum: FFMA + MUFU + FADD per element
            s0 += ex2f(fmaf(v0.x, L2E, negC));
            s1 += ex2f(fmaf(v0.y, L2E, negC));
            s0 += ex2f(fmaf(v0.z, L2E, negC));
            s1 += ex2f(fmaf(v0.w, L2E, negC));
            s0 += ex2f(fmaf(v1.x, L2E, negC));
            s1 += ex2f(fmaf(v1.y, L2E, negC));
            s0 += ex2f(fmaf(v1.z, L2E, negC));
            s1 += ex2f(fmaf(v1.w, L2E, negC));
            s0 += ex2f(fmaf(v2.x, L2E, negC));
            s1 += ex2f(fmaf(v2.y, L2E, negC));
            s0 += ex2f(fmaf(v2.z, L2E, negC));
            s1 += ex2f(fmaf(v2.w, L2E, negC));
            s0 += ex2f(fmaf(v3.x, L2E, negC));
            s1 += ex2f(fmaf(v3.y, L2E, negC));
            s0 += ex2f(fmaf(v3.z, L2E, negC));
            s1 += ex2f(fmaf(v3.w, L2E, negC));

            p4 += 4 * THREADS;
        }

        // ---- scalar tail ----
        for (int i = pre + vecElems + tid; i < V; i += THREADS) {
            float x = __ldg(row + i);
            s0 += ex2f(fmaf(x, L2E, negC));
            PUSH(x, i);
        }
#undef PUSH

        // ---- warp reduce (uniform base) ----
        float s = s0 + s1;
#pragma unroll
        for (int off = 16; off; off >>= 1)
            s += __shfl_xor_sync(FULLM, s, off);
        if (lane == 0) s_wS[w] = s;
        __syncthreads();                       // (A) pushes + sums + prefetch visible

        // ---- warp 0: top-5 + row loss ----
        if (w == 0) {
            float tv[TOPK]; int ti[TOPK];
#pragma unroll
            for (int k = 0; k < TOPK; ++k) { tv[k] = NEG_INF; ti[k] = 0; }

            int cnt = s_cnt;
            __syncwarp();
            if (cnt >= TOPK && cnt <= CAP) {
                for (int base = 0; base < cnt; base += 32) {
                    int i = base + lane;
                    float x = (i < cnt) ? s_vals[i] : NEG_INF;
                    int  id = (i < cnt) ? s_idx[i]  : 0;
                    unsigned bal = __ballot_sync(FULLM, x > tv[TOPK - 1]);
                    while (bal) {
                        int L = __ffs(bal) - 1; bal &= bal - 1;
                        float xv = __shfl_sync(FULLM, x, L);
                        int   iv = __shfl_sync(FULLM, id, L);
                        if (xv > tv[TOPK - 1]) insert5(tv, ti, xv, iv);
                    }
                }
            } else {
                // exact fallback (astronomically rare)
                for (int i0 = 0; i0 < V; i0 += 32) {
                    int i = i0 + lane;
                    float x = (i < V) ? __ldg(row + i) : NEG_INF;
                    unsigned bal = __ballot_sync(FULLM, x > tv[TOPK - 1]);
                    while (bal) {
                        int L = __ffs(bal) - 1; bal &= bal - 1;
                        float xv = __shfl_sync(FULLM, x, L);
                        if (xv > tv[TOPK - 1]) insert5(tv, ti, xv, i0 + L);
                    }
                }
            }

            if (lane == 0) {
                float sf = 0.0f;
                for (int ww = 0; ww < NWARP; ++ww) sf += s_wS[ww];

                float lse  = (-negC + lg2f(sf)) * LN2;
                float nll_cmd = lse - s_xlab;      // prefetched at row start

#pragma unroll
                for (int c = 0; c < NCAT; ++c) s_cat[c] = 0.0f;
#pragma unroll
                for (int k = 0; k < TOPK; ++k)
                    s_cat[s_c2c[ti[k] % ncmd]] += tv[k];

                float mxc = s_cat[0];
#pragma unroll
                for (int c = 1; c < NCAT; ++c) mxc = fmaxf(mxc, s_cat[c]);
                float ssum = 0.0f;
#pragma unroll
                for (int c = 0; c < NCAT; ++c) ssum += ex2f((s_cat[c] - mxc) * L2E);
                float nll_cat = lg2f(ssum) * LN2 + mxc - s_cat[s_cl];

                g_rowloss[b] = 0.6f * nll_cmd + 0.4f * nll_cat;
                s_cnt = 0;                    // reset for next row (sole reader)
            }
        }
        __syncthreads();                       // (B) epilogue + reset done
    }
    // ================= end row loop =================

    // completion protocol: once per CTA
    if (tid == 0) {
        __threadfence();
        unsigned int prev = atomicAdd(&g_done, 1u);
        s_isLast = (prev == (unsigned int)(gridDim.x - 1));
    }
    __syncthreads();

    if (s_isLast) {
        __threadfence();
        float a = 0.0f;
        for (int i = tid; i < B; i += THREADS) a += g_rowloss[i];
        s_red[tid] = a;
        __syncthreads();
#pragma unroll
        for (int off = THREADS / 2; off; off >>= 1) {
            if (tid < off) s_red[tid] += s_red[tid + off];
            __syncthreads();
        }
        if (tid == 0) {
            out[0] = s_red[0] * (1.0f / (float)B);
            atomicExch(&g_done, 0u);
        }
    }
}

extern "C" void kernel_launch(void* const* d_in, const int* in_sizes, int n_in,
                              void* d_out, int out_size)
{
    const float* logits = (const float*)d_in[0];
    const int*   labels = (const int*)d_in[1];
    const int*   catlab = (const int*)d_in[2];
    const int*   c2c    = (const int*)d_in[3];

    const int B    = in_sizes[1];
    const int V    = in_sizes[0] / B;
    const int ncmd = in_sizes[3];

    int grid = GRID < B ? GRID : B;
    hier_loss_fused<<<grid, THREADS>>>(logits, labels, catlab, c2c,
                                       (float*)d_out, V, ncmd, B);
}